// round 5
// baseline (speedup 1.0000x reference)
#include <cuda_runtime.h>
#include <math.h>

// ---------------- problem constants ----------------
#define BN   4
#define TN   16000
#define NCN  80
#define NRN  64
#define NLN  16
#define TT   128     // t-tile for layer + gemm kernels

// ---------------- device scratch (static, no dynamic alloc) ----------------
__device__ float g_cond[BN * NCN * TN];            //  [b][c][t]   20.5 MB
__device__ float g_x0  [BN * NRN * TN];            //  [b][k][t]   16.4 MB
__device__ float g_x1  [BN * NRN * TN];
__device__ float g_acts[NLN * BN * NRN * TN];      //  [i][b][k][t] 262 MB
__device__ float g_h1  [BN * 256 * TN];            //  [b][o][t]   65.5 MB
__device__ float g_h2  [BN * 256 * TN];

typedef unsigned long long ull;

// ---------------- packed f32x2 helpers (sm_103a FFMA2) ----------------
__device__ __forceinline__ void ffma2(ull& d, ull a, ull b) {
    asm("fma.rn.f32x2 %0, %1, %2, %0;" : "+l"(d) : "l"(a), "l"(b));
}
__device__ __forceinline__ ull add2(ull a, ull b) {
    ull r; asm("add.rn.f32x2 %0, %1, %2;" : "=l"(r) : "l"(a), "l"(b)); return r;
}
__device__ __forceinline__ ull pk2(float x, float y) {
    ull r; asm("mov.b64 %0, {%1, %2};" : "=l"(r) : "f"(x), "f"(y)); return r;
}
__device__ __forceinline__ ull bcast2(float x) {
    ull r; asm("mov.b64 %0, {%1, %1};" : "=l"(r) : "f"(x)); return r;
}
__device__ __forceinline__ float2 up2(ull v) {
    float2 f; asm("mov.b64 {%0, %1}, %2;" : "=f"(f.x), "=f"(f.y) : "l"(v)); return f;
}

// ---------------- fast activations ----------------
__device__ __forceinline__ float fast_sigmoid(float x) {
    return __fdividef(1.0f, 1.0f + __expf(-x));
}
__device__ __forceinline__ float fast_tanh(float x) {
    float ax = fabsf(x);
    float e  = __expf(-2.0f * ax);
    float t  = __fdividef(1.0f - e, 1.0f + e);
    return copysignf(t, x);
}

// ===========================================================================
// Kernel 1: transposed-conv upsampler by output phase (640 thr, FFMA2).
//   thread = (b, oh, q); o-dim packed into 20 f32x2 accumulators.
// ===========================================================================
#define UPS_SMEM_FLOATS (25600 + 25600)
__global__ __launch_bounds__(640, 1)
void k_upsample(const float* __restrict__ features,
                const float* __restrict__ up_w,
                const float* __restrict__ up_b)
{
    extern __shared__ float sm[];
    float* ws = sm;            // [j][i][o] : 4*80*80
    float* fs = sm + 25600;    // [b][i][s] : 4*80*80

    const int r   = blockIdx.x;
    const int tid = threadIdx.x;

    for (int n = tid; n < 25600; n += 640) fs[n] = features[n];
    for (int n = tid; n < 25600; n += 640) {
        int j = n / 6400, rem = n % 6400, i = rem / 80, o = rem % 80;
        ws[n] = up_w[(i * 80 + o) * 800 + 200 * j + r];
    }
    __syncthreads();

    const int b  = tid / 160;
    const int oh = (tid % 160) / 80;
    const int q  = tid % 80;
    const int t  = 200 * q + r;

    ull acc[20];
    #pragma unroll
    for (int o2 = 0; o2 < 20; o2++)
        acc[o2] = pk2(__ldg(&up_b[oh * 40 + 2 * o2]), __ldg(&up_b[oh * 40 + 2 * o2 + 1]));

    #pragma unroll
    for (int j = 0; j < 4; j++) {
        int s = q - j;
        if (s >= 0) {
            const float* fsb = fs + b * 6400 + s;
            const float* wsj = ws + j * 6400 + oh * 40;
            #pragma unroll 2
            for (int i = 0; i < 80; i++) {
                ull f = bcast2(fsb[i * 80]);
                const ull* w = (const ull*)(wsj + i * 80);
                #pragma unroll
                for (int o2 = 0; o2 < 20; o2++) ffma2(acc[o2], w[o2], f);
            }
        }
    }
    float* outp = g_cond + (size_t)(b * 80 + oh * 40) * TN + t;
    #pragma unroll
    for (int o2 = 0; o2 < 20; o2++) {
        float2 v = up2(acc[o2]);
        outp[(size_t)(2 * o2) * TN]     = v.x;
        outp[(size_t)(2 * o2 + 1) * TN] = v.y;
    }
}

// ===========================================================================
// Kernel 2: embedding gather  x0[b][k][t] = emb[fi[b][t]][k]
// ===========================================================================
__global__ void k_embed(const int* __restrict__ fi,
                        const float* __restrict__ emb)
{
    int b = blockIdx.y;
    int t = blockIdx.x * 256 + threadIdx.x;
    if (t >= TN) return;
    int idx = fi[b * TN + t];
    const float* row = emb + idx * 64;
    float* out = g_x0 + (size_t)(b * 64) * TN + t;
    #pragma unroll
    for (int k = 0; k < 64; k++) out[(size_t)k * TN] = __ldg(row + k);
}

// ===========================================================================
// Kernel 3: one gated WaveNet layer (1024 threads, FFMA2).
//   tx = tid&15 -> t chunks {tx*4, 64+tx*4}; oy = tid>>4 (0..63) -> gate-pair
//   rows {oy} (tanh) and {64+oy} (sigmoid); res row oy.
// ===========================================================================
#define L_DW0   0
#define L_DW1   8192
#define L_CW    16384
#define L_RW    26624
#define L_GB    30720
#define L_RB    30848
#define L_XE    30912          // [64][256]
#define L_SC    47296          // [80][128]  (reused as acts tile [64][128])
#define LAYER_SMEM_FLOATS 57536

__global__ __launch_bounds__(1024, 1)
void k_layer(const float* __restrict__ dil_w, const float* __restrict__ dil_b,
             const float* __restrict__ cond_w, const float* __restrict__ cond_b,
             const float* __restrict__ res_w,  const float* __restrict__ res_b,
             int li)
{
    extern __shared__ float sm[];
    float* dw0 = sm + L_DW0;
    float* dw1 = sm + L_DW1;
    float* cw  = sm + L_CW;
    float* rw  = sm + L_RW;
    float* gb  = sm + L_GB;
    float* rb  = sm + L_RB;
    float* xe  = sm + L_XE;
    float* sc  = sm + L_SC;
    float* sa  = sm + L_SC;     // overlapped, separated by a barrier

    const int tid = threadIdx.x;
    const int t0  = blockIdx.x * TT;
    const int b   = blockIdx.y;
    const int d   = 1 << (li & 7);
    const int has_res = (li < NLN - 1);

    const float* xin  = (li & 1) ? g_x1 : g_x0;
    float*       xout = (li & 1) ? g_x0 : g_x1;
    float*       acts = g_acts + (size_t)li * BN * NRN * TN;

    const float* dwb = dil_w + (size_t)li * 16384;
    const float* dbb = dil_b + li * 128;
    const float* cwb = cond_w + (size_t)li * 128 * 80;
    const float* cbb = cond_b + li * 128;

    // ---- staging ----
    for (int n = tid; n < 8192; n += 1024) {
        float2 v = ((const float2*)dwb)[n];
        dw0[n] = v.x; dw1[n] = v.y;
    }
    for (int n = tid; n < 10240; n += 1024) cw[n] = cwb[n];
    if (has_res) {
        const float* rwb = res_w + (size_t)li * 4096;
        for (int n = tid; n < 4096; n += 1024) rw[n] = rwb[n];
        if (tid < 64) rb[tid] = res_b[li * 64 + tid];
    }
    if (tid < 128) gb[tid] = dbb[tid] + cbb[tid];

    if (t0 == 0) {
        for (int n = tid; n < 64 * 256; n += 1024) {
            int k = n >> 8, tt = n & 255;
            int gt = t0 - 128 + tt;
            xe[n] = (gt >= 0) ? xin[(size_t)(b * 64 + k) * TN + gt] : 0.0f;
        }
    } else {
        for (int n = tid * 4; n < 64 * 256; n += 4096) {
            int k = n >> 8, tt = n & 255;
            *(float4*)&xe[n] = *(const float4*)&xin[(size_t)(b * 64 + k) * TN + t0 - 128 + tt];
        }
    }
    for (int n = tid * 4; n < 80 * TT; n += 4096) {
        int c = n >> 7, tt = n & 127;
        *(float4*)&sc[n] = *(const float4*)&g_cond[(size_t)(b * 80 + c) * TN + t0 + tt];
    }
    __syncthreads();

    const int tx = tid & 15, oy = tid >> 4;   // oy 0..63
    const int c0 = tx * 4, c1 = 64 + tx * 4;

    ull at[4], as_[4];
    {
        ull bt = bcast2(gb[oy]);
        ull bs = bcast2(gb[64 + oy]);
        #pragma unroll
        for (int p = 0; p < 4; p++) { at[p] = bt; as_[p] = bs; }
    }

    // ---- dilated-pair GEMM (K=64, two operands per k) ----
    const int dm4 = (d & 3) == 0;
    #pragma unroll 2
    for (int k = 0; k < 64; k++) {
        const float* xr = xe + k * 256;
        ull xc[4], xp[4];
        {
            ulonglong2 v0 = *(const ulonglong2*)&xr[128 + c0];
            ulonglong2 v1 = *(const ulonglong2*)&xr[128 + c1];
            xc[0] = v0.x; xc[1] = v0.y; xc[2] = v1.x; xc[3] = v1.y;
        }
        if (dm4) {
            ulonglong2 v0 = *(const ulonglong2*)&xr[128 - d + c0];
            ulonglong2 v1 = *(const ulonglong2*)&xr[128 - d + c1];
            xp[0] = v0.x; xp[1] = v0.y; xp[2] = v1.x; xp[3] = v1.y;
        } else if (d == 2) {
            xp[0] = *(const ull*)&xr[126 + c0];
            xp[1] = *(const ull*)&xr[128 + c0];
            xp[2] = *(const ull*)&xr[126 + c1];
            xp[3] = *(const ull*)&xr[128 + c1];
        } else { // d == 1
            xp[0] = pk2(xr[127 + c0], xr[128 + c0]);
            xp[1] = pk2(xr[129 + c0], xr[130 + c0]);
            xp[2] = pk2(xr[127 + c1], xr[128 + c1]);
            xp[3] = pk2(xr[129 + c1], xr[130 + c1]);
        }
        const int rt = oy * 64 + k;
        const int rs = (64 + oy) * 64 + k;
        ull w0t = bcast2(dw0[rt]), w1t = bcast2(dw1[rt]);
        ull w0s = bcast2(dw0[rs]), w1s = bcast2(dw1[rs]);
        #pragma unroll
        for (int p = 0; p < 4; p++) {
            ffma2(at[p],  w0t, xp[p]);  ffma2(at[p],  w1t, xc[p]);
            ffma2(as_[p], w0s, xp[p]);  ffma2(as_[p], w1s, xc[p]);
        }
    }

    // ---- cond GEMM (K=80) ----
    #pragma unroll 2
    for (int c = 0; c < 80; c++) {
        const float* scr = sc + c * TT;
        ulonglong2 v0 = *(const ulonglong2*)&scr[c0];
        ulonglong2 v1 = *(const ulonglong2*)&scr[c1];
        ull xc[4] = { v0.x, v0.y, v1.x, v1.y };
        ull wt = bcast2(cw[oy * 80 + c]);
        ull wg = bcast2(cw[(64 + oy) * 80 + c]);
        #pragma unroll
        for (int p = 0; p < 4; p++) {
            ffma2(at[p], wt, xc[p]);
            ffma2(as_[p], wg, xc[p]);
        }
    }

    // ---- gating ----
    float av[8];
    #pragma unroll
    for (int p = 0; p < 4; p++) {
        float2 t2 = up2(at[p]);
        float2 s2 = up2(as_[p]);
        av[2 * p]     = fast_tanh(t2.x) * fast_sigmoid(s2.x);
        av[2 * p + 1] = fast_tanh(t2.y) * fast_sigmoid(s2.y);
    }

    __syncthreads();   // done reading sc; region becomes sa

    {
        float4 q0 = make_float4(av[0], av[1], av[2], av[3]);
        float4 q1 = make_float4(av[4], av[5], av[6], av[7]);
        *(float4*)&sa[oy * TT + c0] = q0;
        *(float4*)&sa[oy * TT + c1] = q1;
        float* gp = acts + (size_t)(b * 64 + oy) * TN + t0;
        *(float4*)&gp[c0] = q0;
        *(float4*)&gp[c1] = q1;
    }
    if (!has_res) return;
    __syncthreads();

    // ---- residual GEMM (K=64) + x add ----
    ull rc[4];
    {
        ull bv = bcast2(rb[oy]);
        #pragma unroll
        for (int p = 0; p < 4; p++) rc[p] = bv;
    }
    #pragma unroll 2
    for (int k = 0; k < 64; k++) {
        const float* ar = sa + k * TT;
        ulonglong2 v0 = *(const ulonglong2*)&ar[c0];
        ulonglong2 v1 = *(const ulonglong2*)&ar[c1];
        ull w = bcast2(rw[oy * 64 + k]);
        ffma2(rc[0], w, v0.x);  ffma2(rc[1], w, v0.y);
        ffma2(rc[2], w, v1.x);  ffma2(rc[3], w, v1.y);
    }
    {
        const float* xr = xe + oy * 256 + 128;
        ulonglong2 x0v = *(const ulonglong2*)&xr[c0];
        ulonglong2 x1v = *(const ulonglong2*)&xr[c1];
        ulonglong2 o0, o1;
        o0.x = add2(rc[0], x0v.x);  o0.y = add2(rc[1], x0v.y);
        o1.x = add2(rc[2], x1v.x);  o1.y = add2(rc[3], x1v.y);
        float* gp = xout + (size_t)(b * 64 + oy) * TN + t0;
        *(ulonglong2*)&gp[c0] = o0;
        *(ulonglong2*)&gp[c1] = o1;
    }
}

// ===========================================================================
// Kernel 4: generic 128-row x 128-t GEMM over K = kchunks*64 (1024 thr, FFMA2).
//   bsel: 0 -> g_acts, 1 -> g_h1, 2 -> g_h2 ; dsel: 0 -> g_h1, 1 -> g_h2,
//   2 -> d_out with right-shift by one t.
// ===========================================================================
#define GEMM_SMEM_FLOATS (8192 + 8192 + 128)
__global__ __launch_bounds__(1024, 1)
void k_gemm(const float* __restrict__ A,
            float* __restrict__ dptr,            // only for dsel==2
            const float* __restrict__ biassrc,   // skip_b or nullptr
            int kchunks, int as_r, int as_c,
            long bs_b, long bs_c,
            int bsel, int dsel, int do_relu)
{
    extern __shared__ float sm[];
    float* wA    = sm;            // [128][64]
    float* sB    = sm + 8192;     // [64][128]
    float* sbias = sm + 16384;    // [128]

    const int tid = threadIdx.x;
    const int t0  = blockIdx.x * TT;
    const int mh  = blockIdx.y;
    const int b   = blockIdx.z;

    const float* Bsrc = (bsel == 0) ? g_acts : (bsel == 1) ? g_h1 : g_h2;
    float* D = (dsel == 0) ? g_h1 : (dsel == 1) ? g_h2 : dptr;

    if (tid < 128) {
        float s = 0.0f;
        if (biassrc)
            for (int i = 0; i < 16; i++) s += biassrc[i * 256 + mh * 128 + tid];
        sbias[tid] = s;
    }

    const int tx = tid & 15, oy = tid >> 4;   // oy 0..63, rows 2*oy+rr
    const int c0 = tx * 4, c1 = 64 + tx * 4;

    ull acc[2][4];
    #pragma unroll
    for (int rr = 0; rr < 2; rr++)
        #pragma unroll
        for (int p = 0; p < 4; p++) acc[rr][p] = 0ULL;

    for (int ci = 0; ci < kchunks; ci++) {
        __syncthreads();
        const float* Ab = A + (size_t)(mh * 128) * as_r + (size_t)ci * as_c;
        for (int n = tid * 4; n < 8192; n += 4096) {
            int r = n >> 6, kk = n & 63;
            *(float4*)&wA[n] = *(const float4*)&Ab[(size_t)r * as_r + kk];
        }
        const float* Bb = Bsrc + (long)b * bs_b + (long)ci * bs_c + t0;
        for (int n = tid * 4; n < 8192; n += 4096) {
            int kk = n >> 7, tt = n & 127;
            *(float4*)&sB[n] = *(const float4*)&Bb[(size_t)kk * TN + tt];
        }
        __syncthreads();

        #pragma unroll 2
        for (int k = 0; k < 64; k++) {
            const float* br = sB + k * TT;
            ulonglong2 v0 = *(const ulonglong2*)&br[c0];
            ulonglong2 v1 = *(const ulonglong2*)&br[c1];
            ull a0 = bcast2(wA[(2 * oy) * 64 + k]);
            ull a1 = bcast2(wA[(2 * oy + 1) * 64 + k]);
            ffma2(acc[0][0], a0, v0.x);  ffma2(acc[0][1], a0, v0.y);
            ffma2(acc[0][2], a0, v1.x);  ffma2(acc[0][3], a0, v1.y);
            ffma2(acc[1][0], a1, v0.x);  ffma2(acc[1][1], a1, v0.y);
            ffma2(acc[1][2], a1, v1.x);  ffma2(acc[1][3], a1, v1.y);
        }
    }

    #pragma unroll
    for (int rr = 0; rr < 2; rr++) {
        int row = 2 * oy + rr;
        float bias = sbias[row];
        float v[8];
        #pragma unroll
        for (int p = 0; p < 4; p++) {
            float2 f = up2(acc[rr][p]);
            v[2 * p]     = f.x + bias;
            v[2 * p + 1] = f.y + bias;
        }
        if (do_relu) {
            #pragma unroll
            for (int j = 0; j < 8; j++) v[j] = fmaxf(v[j], 0.0f);
        }
        size_t rbase = (size_t)(b * 256 + mh * 128 + row) * TN;
        if (dsel != 2) {
            *(float4*)&D[rbase + t0 + c0] = make_float4(v[0], v[1], v[2], v[3]);
            *(float4*)&D[rbase + t0 + c1] = make_float4(v[4], v[5], v[6], v[7]);
        } else {
            #pragma unroll
            for (int j = 0; j < 8; j++) {
                int t = t0 + ((j < 4) ? c0 + j : c1 + j - 4);
                if (t + 1 < TN) D[rbase + t + 1] = v[j];
                if (t == 0)     D[rbase] = 0.0f;
            }
        }
    }
}

// ===========================================================================
// launcher
// ===========================================================================
extern "C" void kernel_launch(void* const* d_in, const int* in_sizes, int n_in,
                              void* d_out, int out_size)
{
    const float* features = (const float*)d_in[0];
    const int*   fwd      = (const int*)  d_in[1];
    const float* emb      = (const float*)d_in[2];
    const float* up_w     = (const float*)d_in[3];
    const float* up_b     = (const float*)d_in[4];
    const float* cond_w   = (const float*)d_in[5];
    const float* cond_b   = (const float*)d_in[6];
    const float* dil_w    = (const float*)d_in[7];
    const float* dil_b    = (const float*)d_in[8];
    const float* res_w    = (const float*)d_in[9];
    const float* res_b    = (const float*)d_in[10];
    const float* skip_w   = (const float*)d_in[11];
    const float* skip_b   = (const float*)d_in[12];
    const float* out_w    = (const float*)d_in[13];
    const float* end_w    = (const float*)d_in[14];
    float* out = (float*)d_out;

    cudaFuncSetAttribute(k_upsample, cudaFuncAttributeMaxDynamicSharedMemorySize,
                         UPS_SMEM_FLOATS * 4);
    cudaFuncSetAttribute(k_layer, cudaFuncAttributeMaxDynamicSharedMemorySize,
                         LAYER_SMEM_FLOATS * 4);
    cudaFuncSetAttribute(k_gemm, cudaFuncAttributeMaxDynamicSharedMemorySize,
                         GEMM_SMEM_FLOATS * 4);

    k_upsample<<<200, 640, UPS_SMEM_FLOATS * 4>>>(features, up_w, up_b);
    k_embed<<<dim3((TN + 255) / 256, BN), 256>>>(fwd, emb);

    for (int i = 0; i < NLN; i++) {
        k_layer<<<dim3(TN / TT, BN), 1024, LAYER_SMEM_FLOATS * 4>>>(
            dil_w, dil_b, cond_w, cond_b, res_w, res_b, i);
    }

    // skip-sum GEMM: h1 = relu(SW[256x1024] @ ACTS + sum_i skip_b)
    k_gemm<<<dim3(TN / TT, 2, BN), 1024, GEMM_SMEM_FLOATS * 4>>>(
        skip_w, nullptr, skip_b,
        /*kchunks=*/16, /*as_r=*/64, /*as_c=*/16384,
        /*bs_b=*/(long)64 * TN, /*bs_c=*/(long)4 * 64 * TN,
        /*bsel=*/0, /*dsel=*/0, /*relu=*/1);

    // h2 = relu(out_w @ h1)
    k_gemm<<<dim3(TN / TT, 2, BN), 1024, GEMM_SMEM_FLOATS * 4>>>(
        out_w, nullptr, nullptr,
        /*kchunks=*/4, /*as_r=*/256, /*as_c=*/64,
        /*bs_b=*/(long)256 * TN, /*bs_c=*/(long)64 * TN,
        /*bsel=*/1, /*dsel=*/1, /*relu=*/1);

    // out = shift_right(end_w @ h2)
    k_gemm<<<dim3(TN / TT, 2, BN), 1024, GEMM_SMEM_FLOATS * 4>>>(
        end_w, out, nullptr,
        /*kchunks=*/4, /*as_r=*/256, /*as_c=*/64,
        /*bs_b=*/(long)256 * TN, /*bs_c=*/(long)64 * TN,
        /*bsel=*/2, /*dsel=*/2, /*relu=*/0);
}

// round 6
// speedup vs baseline: 1.2361x; 1.2361x over previous
#include <cuda_runtime.h>
#include <math.h>

// ---------------- problem constants ----------------
#define BN   4
#define TN   16000
#define NCN  80
#define NRN  64
#define NLN  16
#define TT   128     // t-tile for layer + gemm kernels

// ---------------- device scratch (static, no dynamic alloc) ----------------
__device__ float g_cond[BN * NCN * TN];            //  [b][c][t]   20.5 MB
__device__ float g_x0  [BN * NRN * TN];            //  [b][k][t]   16.4 MB
__device__ float g_x1  [BN * NRN * TN];
__device__ float g_acts[NLN * BN * NRN * TN];      //  [i][b][k][t] 262 MB
__device__ float g_h1  [BN * 256 * TN];            //  [b][o][t]   65.5 MB
__device__ float g_h2  [BN * 256 * TN];

typedef unsigned long long ull;

// ---------------- packed f32x2 helpers (sm_103a FFMA2) ----------------
__device__ __forceinline__ void ffma2(ull& d, ull a, ull b) {
    asm("fma.rn.f32x2 %0, %1, %2, %0;" : "+l"(d) : "l"(a), "l"(b));
}
__device__ __forceinline__ ull add2(ull a, ull b) {
    ull r; asm("add.rn.f32x2 %0, %1, %2;" : "=l"(r) : "l"(a), "l"(b)); return r;
}
__device__ __forceinline__ ull pk2(float x, float y) {
    ull r; asm("mov.b64 %0, {%1, %2};" : "=l"(r) : "f"(x), "f"(y)); return r;
}
__device__ __forceinline__ ull bcast2(float x) {
    ull r; asm("mov.b64 %0, {%1, %1};" : "=l"(r) : "f"(x)); return r;
}
__device__ __forceinline__ float2 up2(ull v) {
    float2 f; asm("mov.b64 {%0, %1}, %2;" : "=f"(f.x), "=f"(f.y) : "l"(v)); return f;
}

// ---------------- fast activations ----------------
__device__ __forceinline__ float fast_sigmoid(float x) {
    return __fdividef(1.0f, 1.0f + __expf(-x));
}
__device__ __forceinline__ float fast_tanh(float x) {
    float ax = fabsf(x);
    float e  = __expf(-2.0f * ax);
    float t  = __fdividef(1.0f - e, 1.0f + e);
    return copysignf(t, x);
}

// ===========================================================================
// Kernel 1: transposed-conv upsampler by output phase (640 thr, FFMA2).
// ===========================================================================
#define UPS_SMEM_FLOATS (25600 + 25600)
__global__ __launch_bounds__(640, 1)
void k_upsample(const float* __restrict__ features,
                const float* __restrict__ up_w,
                const float* __restrict__ up_b)
{
    extern __shared__ float sm[];
    float* ws = sm;            // [j][i][o] : 4*80*80
    float* fs = sm + 25600;    // [b][i][s] : 4*80*80

    const int r   = blockIdx.x;
    const int tid = threadIdx.x;

    for (int n = tid; n < 25600; n += 640) fs[n] = features[n];
    for (int n = tid; n < 25600; n += 640) {
        int j = n / 6400, rem = n % 6400, i = rem / 80, o = rem % 80;
        ws[n] = up_w[(i * 80 + o) * 800 + 200 * j + r];
    }
    __syncthreads();

    const int b  = tid / 160;
    const int oh = (tid % 160) / 80;
    const int q  = tid % 80;
    const int t  = 200 * q + r;

    ull acc[20];
    #pragma unroll
    for (int o2 = 0; o2 < 20; o2++)
        acc[o2] = pk2(__ldg(&up_b[oh * 40 + 2 * o2]), __ldg(&up_b[oh * 40 + 2 * o2 + 1]));

    #pragma unroll
    for (int j = 0; j < 4; j++) {
        int s = q - j;
        if (s >= 0) {
            const float* fsb = fs + b * 6400 + s;
            const float* wsj = ws + j * 6400 + oh * 40;
            #pragma unroll 2
            for (int i = 0; i < 80; i++) {
                ull f = bcast2(fsb[i * 80]);
                const ull* w = (const ull*)(wsj + i * 80);
                #pragma unroll
                for (int o2 = 0; o2 < 20; o2++) ffma2(acc[o2], w[o2], f);
            }
        }
    }
    float* outp = g_cond + (size_t)(b * 80 + oh * 40) * TN + t;
    #pragma unroll
    for (int o2 = 0; o2 < 20; o2++) {
        float2 v = up2(acc[o2]);
        outp[(size_t)(2 * o2) * TN]     = v.x;
        outp[(size_t)(2 * o2 + 1) * TN] = v.y;
    }
}

// ===========================================================================
// Kernel 2: embedding gather  x0[b][k][t] = emb[fi[b][t]][k]
// ===========================================================================
__global__ void k_embed(const int* __restrict__ fi,
                        const float* __restrict__ emb)
{
    int b = blockIdx.y;
    int t = blockIdx.x * 256 + threadIdx.x;
    if (t >= TN) return;
    int idx = fi[b * TN + t];
    const float* row = emb + idx * 64;
    float* out = g_x0 + (size_t)(b * 64) * TN + t;
    #pragma unroll
    for (int k = 0; k < 64; k++) out[(size_t)k * TN] = __ldg(row + k);
}

// ===========================================================================
// Kernel 3: one gated WaveNet layer (256 threads, 8 rows/thread, FFMA2).
//   tx = tid&15 -> t chunks {tx*4, 64+tx*4}
//   oy = tid>>4 (0..15) -> tanh rows {4oy..4oy+3}, sigmoid rows {64+4oy..}
//   64 FFMA2 per k on 64 B of LDS data: crossbar ~25% of FMA demand.
// ===========================================================================
#define L_DW0   0
#define L_DW1   8192
#define L_CW    16384
#define L_RW    26624
#define L_GB    30720
#define L_RB    30848
#define L_XE    30912          // [64][256]
#define L_SC    47296          // [80][128]  (reused as acts tile [64][128])
#define LAYER_SMEM_FLOATS 57536

__global__ __launch_bounds__(256, 1)
void k_layer(const float* __restrict__ dil_w, const float* __restrict__ dil_b,
             const float* __restrict__ cond_w, const float* __restrict__ cond_b,
             const float* __restrict__ res_w,  const float* __restrict__ res_b,
             int li)
{
    extern __shared__ float sm[];
    float* dw0 = sm + L_DW0;
    float* dw1 = sm + L_DW1;
    float* cw  = sm + L_CW;
    float* rw  = sm + L_RW;
    float* gb  = sm + L_GB;
    float* rb  = sm + L_RB;
    float* xe  = sm + L_XE;
    float* sc  = sm + L_SC;
    float* sa  = sm + L_SC;     // overlapped, separated by a barrier

    const int tid = threadIdx.x;
    const int t0  = blockIdx.x * TT;
    const int b   = blockIdx.y;
    const int d   = 1 << (li & 7);
    const int has_res = (li < NLN - 1);

    const float* xin  = (li & 1) ? g_x1 : g_x0;
    float*       xout = (li & 1) ? g_x0 : g_x1;
    float*       acts = g_acts + (size_t)li * BN * NRN * TN;

    const float* dwb = dil_w + (size_t)li * 16384;
    const float* dbb = dil_b + li * 128;
    const float* cwb = cond_w + (size_t)li * 128 * 80;
    const float* cbb = cond_b + li * 128;

    // ---- staging ----
    for (int n = tid; n < 8192; n += 256) {
        float2 v = ((const float2*)dwb)[n];
        dw0[n] = v.x; dw1[n] = v.y;
    }
    for (int n = tid; n < 10240; n += 256) cw[n] = cwb[n];
    if (has_res) {
        const float* rwb = res_w + (size_t)li * 4096;
        for (int n = tid; n < 4096; n += 256) rw[n] = rwb[n];
        if (tid < 64) rb[tid] = res_b[li * 64 + tid];
    }
    if (tid < 128) gb[tid] = dbb[tid] + cbb[tid];

    if (t0 == 0) {
        for (int n = tid; n < 64 * 256; n += 256) {
            int k = n >> 8, tt = n & 255;
            int gt = t0 - 128 + tt;
            xe[n] = (gt >= 0) ? xin[(size_t)(b * 64 + k) * TN + gt] : 0.0f;
        }
    } else {
        for (int n = tid * 4; n < 64 * 256; n += 1024) {
            int k = n >> 8, tt = n & 255;
            *(float4*)&xe[n] = *(const float4*)&xin[(size_t)(b * 64 + k) * TN + t0 - 128 + tt];
        }
    }
    for (int n = tid * 4; n < 80 * TT; n += 1024) {
        int c = n >> 7, tt = n & 127;
        *(float4*)&sc[n] = *(const float4*)&g_cond[(size_t)(b * 80 + c) * TN + t0 + tt];
    }
    __syncthreads();

    const int tx = tid & 15, oy = tid >> 4;   // oy 0..15
    const int c0 = tx * 4, c1 = 64 + tx * 4;

    ull at[4][4], as_[4][4];
    #pragma unroll
    for (int rr = 0; rr < 4; rr++) {
        ull bt = bcast2(gb[4 * oy + rr]);
        ull bs = bcast2(gb[64 + 4 * oy + rr]);
        #pragma unroll
        for (int p = 0; p < 4; p++) { at[rr][p] = bt; as_[rr][p] = bs; }
    }

    // ---- dilated-pair GEMM (K=64, two operands per k) ----
    const int dm4 = (d & 3) == 0;
    #pragma unroll 2
    for (int k = 0; k < 64; k++) {
        const float* xr = xe + k * 256;
        ull xc[4], xp[4];
        {
            ulonglong2 v0 = *(const ulonglong2*)&xr[128 + c0];
            ulonglong2 v1 = *(const ulonglong2*)&xr[128 + c1];
            xc[0] = v0.x; xc[1] = v0.y; xc[2] = v1.x; xc[3] = v1.y;
        }
        if (dm4) {
            ulonglong2 v0 = *(const ulonglong2*)&xr[128 - d + c0];
            ulonglong2 v1 = *(const ulonglong2*)&xr[128 - d + c1];
            xp[0] = v0.x; xp[1] = v0.y; xp[2] = v1.x; xp[3] = v1.y;
        } else if (d == 2) {
            xp[0] = *(const ull*)&xr[126 + c0];
            xp[1] = *(const ull*)&xr[128 + c0];
            xp[2] = *(const ull*)&xr[126 + c1];
            xp[3] = *(const ull*)&xr[128 + c1];
        } else { // d == 1
            xp[0] = pk2(xr[127 + c0], xr[128 + c0]);
            xp[1] = pk2(xr[129 + c0], xr[130 + c0]);
            xp[2] = pk2(xr[127 + c1], xr[128 + c1]);
            xp[3] = pk2(xr[129 + c1], xr[130 + c1]);
        }
        #pragma unroll
        for (int rr = 0; rr < 4; rr++) {
            const int rt = (4 * oy + rr) * 64 + k;
            const int rs = (64 + 4 * oy + rr) * 64 + k;
            ull w0t = bcast2(dw0[rt]), w1t = bcast2(dw1[rt]);
            ull w0s = bcast2(dw0[rs]), w1s = bcast2(dw1[rs]);
            #pragma unroll
            for (int p = 0; p < 4; p++) {
                ffma2(at[rr][p],  w0t, xp[p]);  ffma2(at[rr][p],  w1t, xc[p]);
                ffma2(as_[rr][p], w0s, xp[p]);  ffma2(as_[rr][p], w1s, xc[p]);
            }
        }
    }

    // ---- cond GEMM (K=80) ----
    #pragma unroll 2
    for (int c = 0; c < 80; c++) {
        const float* scr = sc + c * TT;
        ulonglong2 v0 = *(const ulonglong2*)&scr[c0];
        ulonglong2 v1 = *(const ulonglong2*)&scr[c1];
        ull xc[4] = { v0.x, v0.y, v1.x, v1.y };
        #pragma unroll
        for (int rr = 0; rr < 4; rr++) {
            ull wt = bcast2(cw[(4 * oy + rr) * 80 + c]);
            ull wg = bcast2(cw[(64 + 4 * oy + rr) * 80 + c]);
            #pragma unroll
            for (int p = 0; p < 4; p++) {
                ffma2(at[rr][p], wt, xc[p]);
                ffma2(as_[rr][p], wg, xc[p]);
            }
        }
    }

    // ---- gating ----
    float av[4][8];
    #pragma unroll
    for (int rr = 0; rr < 4; rr++)
        #pragma unroll
        for (int p = 0; p < 4; p++) {
            float2 t2 = up2(at[rr][p]);
            float2 s2 = up2(as_[rr][p]);
            av[rr][2 * p]     = fast_tanh(t2.x) * fast_sigmoid(s2.x);
            av[rr][2 * p + 1] = fast_tanh(t2.y) * fast_sigmoid(s2.y);
        }

    __syncthreads();   // done reading sc; region becomes sa

    #pragma unroll
    for (int rr = 0; rr < 4; rr++) {
        int row = 4 * oy + rr;
        float4 q0 = make_float4(av[rr][0], av[rr][1], av[rr][2], av[rr][3]);
        float4 q1 = make_float4(av[rr][4], av[rr][5], av[rr][6], av[rr][7]);
        *(float4*)&sa[row * TT + c0] = q0;
        *(float4*)&sa[row * TT + c1] = q1;
        float* gp = acts + (size_t)(b * 64 + row) * TN + t0;
        *(float4*)&gp[c0] = q0;
        *(float4*)&gp[c1] = q1;
    }
    if (!has_res) return;
    __syncthreads();

    // ---- residual GEMM (K=64) + x add ----
    ull rc[4][4];
    #pragma unroll
    for (int rr = 0; rr < 4; rr++) {
        ull bv = bcast2(rb[4 * oy + rr]);
        #pragma unroll
        for (int p = 0; p < 4; p++) rc[rr][p] = bv;
    }
    #pragma unroll 2
    for (int k = 0; k < 64; k++) {
        const float* ar = sa + k * TT;
        ulonglong2 v0 = *(const ulonglong2*)&ar[c0];
        ulonglong2 v1 = *(const ulonglong2*)&ar[c1];
        ull bv[4] = { v0.x, v0.y, v1.x, v1.y };
        #pragma unroll
        for (int rr = 0; rr < 4; rr++) {
            ull w = bcast2(rw[(4 * oy + rr) * 64 + k]);
            #pragma unroll
            for (int p = 0; p < 4; p++) ffma2(rc[rr][p], w, bv[p]);
        }
    }
    #pragma unroll
    for (int rr = 0; rr < 4; rr++) {
        int row = 4 * oy + rr;
        const float* xr = xe + row * 256 + 128;
        ulonglong2 x0v = *(const ulonglong2*)&xr[c0];
        ulonglong2 x1v = *(const ulonglong2*)&xr[c1];
        ulonglong2 o0, o1;
        o0.x = add2(rc[rr][0], x0v.x);  o0.y = add2(rc[rr][1], x0v.y);
        o1.x = add2(rc[rr][2], x1v.x);  o1.y = add2(rc[rr][3], x1v.y);
        float* gp = xout + (size_t)(b * 64 + row) * TN + t0;
        *(ulonglong2*)&gp[c0] = o0;
        *(ulonglong2*)&gp[c1] = o1;
    }
}

// ===========================================================================
// Kernel 4: generic 128-row x 128-t GEMM over K = kchunks*64 (512 thr, FFMA2).
//   bsel: 0 -> g_acts, 1 -> g_h1, 2 -> g_h2 ; dsel: 0 -> g_h1, 1 -> g_h2,
//   2 -> d_out with right-shift by one t.
// ===========================================================================
#define GEMM_SMEM_FLOATS (8192 + 8192 + 128)
__global__ __launch_bounds__(512, 1)
void k_gemm(const float* __restrict__ A,
            float* __restrict__ dptr,            // only for dsel==2
            const float* __restrict__ biassrc,   // skip_b or nullptr
            int kchunks, int as_r, int as_c,
            long bs_b, long bs_c,
            int bsel, int dsel, int do_relu)
{
    extern __shared__ float sm[];
    float* wA    = sm;            // [128][64]
    float* sB    = sm + 8192;     // [64][128]
    float* sbias = sm + 16384;    // [128]

    const int tid = threadIdx.x;
    const int t0  = blockIdx.x * TT;
    const int mh  = blockIdx.y;
    const int b   = blockIdx.z;

    const float* Bsrc = (bsel == 0) ? g_acts : (bsel == 1) ? g_h1 : g_h2;
    float* D = (dsel == 0) ? g_h1 : (dsel == 1) ? g_h2 : dptr;

    if (tid < 128) {
        float s = 0.0f;
        if (biassrc)
            for (int i = 0; i < 16; i++) s += biassrc[i * 256 + mh * 128 + tid];
        sbias[tid] = s;
    }

    const int tx = tid & 15, oy = tid >> 4;   // oy 0..31, rows oy*4+rr
    const int c0 = tx * 4, c1 = 64 + tx * 4;

    ull acc[4][4];
    #pragma unroll
    for (int rr = 0; rr < 4; rr++)
        #pragma unroll
        for (int p = 0; p < 4; p++) acc[rr][p] = 0ULL;

    for (int ci = 0; ci < kchunks; ci++) {
        __syncthreads();
        const float* Ab = A + (size_t)(mh * 128) * as_r + (size_t)ci * as_c;
        for (int n = tid * 4; n < 8192; n += 2048) {
            int r = n >> 6, kk = n & 63;
            *(float4*)&wA[n] = *(const float4*)&Ab[(size_t)r * as_r + kk];
        }
        const float* Bb = Bsrc + (long)b * bs_b + (long)ci * bs_c + t0;
        for (int n = tid * 4; n < 8192; n += 2048) {
            int kk = n >> 7, tt = n & 127;
            *(float4*)&sB[n] = *(const float4*)&Bb[(size_t)kk * TN + tt];
        }
        __syncthreads();

        #pragma unroll 2
        for (int k = 0; k < 64; k++) {
            const float* br = sB + k * TT;
            ulonglong2 v0 = *(const ulonglong2*)&br[c0];
            ulonglong2 v1 = *(const ulonglong2*)&br[c1];
            ull bv[4] = { v0.x, v0.y, v1.x, v1.y };
            #pragma unroll
            for (int rr = 0; rr < 4; rr++) {
                ull a = bcast2(wA[(oy * 4 + rr) * 64 + k]);
                #pragma unroll
                for (int p = 0; p < 4; p++) ffma2(acc[rr][p], a, bv[p]);
            }
        }
    }

    #pragma unroll
    for (int rr = 0; rr < 4; rr++) {
        int row = oy * 4 + rr;
        float bias = sbias[row];
        float v[8];
        #pragma unroll
        for (int p = 0; p < 4; p++) {
            float2 f = up2(acc[rr][p]);
            v[2 * p]     = f.x + bias;
            v[2 * p + 1] = f.y + bias;
        }
        if (do_relu) {
            #pragma unroll
            for (int j = 0; j < 8; j++) v[j] = fmaxf(v[j], 0.0f);
        }
        size_t rbase = (size_t)(b * 256 + mh * 128 + row) * TN;
        if (dsel != 2) {
            *(float4*)&D[rbase + t0 + c0] = make_float4(v[0], v[1], v[2], v[3]);
            *(float4*)&D[rbase + t0 + c1] = make_float4(v[4], v[5], v[6], v[7]);
        } else {
            #pragma unroll
            for (int j = 0; j < 8; j++) {
                int t = t0 + ((j < 4) ? c0 + j : c1 + j - 4);
                if (t + 1 < TN) D[rbase + t + 1] = v[j];
                if (t == 0)     D[rbase] = 0.0f;
            }
        }
    }
}

// ===========================================================================
// launcher
// ===========================================================================
extern "C" void kernel_launch(void* const* d_in, const int* in_sizes, int n_in,
                              void* d_out, int out_size)
{
    const float* features = (const float*)d_in[0];
    const int*   fwd      = (const int*)  d_in[1];
    const float* emb      = (const float*)d_in[2];
    const float* up_w     = (const float*)d_in[3];
    const float* up_b     = (const float*)d_in[4];
    const float* cond_w   = (const float*)d_in[5];
    const float* cond_b   = (const float*)d_in[6];
    const float* dil_w    = (const float*)d_in[7];
    const float* dil_b    = (const float*)d_in[8];
    const float* res_w    = (const float*)d_in[9];
    const float* res_b    = (const float*)d_in[10];
    const float* skip_w   = (const float*)d_in[11];
    const float* skip_b   = (const float*)d_in[12];
    const float* out_w    = (const float*)d_in[13];
    const float* end_w    = (const float*)d_in[14];
    float* out = (float*)d_out;

    cudaFuncSetAttribute(k_upsample, cudaFuncAttributeMaxDynamicSharedMemorySize,
                         UPS_SMEM_FLOATS * 4);
    cudaFuncSetAttribute(k_layer, cudaFuncAttributeMaxDynamicSharedMemorySize,
                         LAYER_SMEM_FLOATS * 4);
    cudaFuncSetAttribute(k_gemm, cudaFuncAttributeMaxDynamicSharedMemorySize,
                         GEMM_SMEM_FLOATS * 4);

    k_upsample<<<200, 640, UPS_SMEM_FLOATS * 4>>>(features, up_w, up_b);
    k_embed<<<dim3((TN + 255) / 256, BN), 256>>>(fwd, emb);

    for (int i = 0; i < NLN; i++) {
        k_layer<<<dim3(TN / TT, BN), 256, LAYER_SMEM_FLOATS * 4>>>(
            dil_w, dil_b, cond_w, cond_b, res_w, res_b, i);
    }

    // skip-sum GEMM: h1 = relu(SW[256x1024] @ ACTS + sum_i skip_b)
    k_gemm<<<dim3(TN / TT, 2, BN), 512, GEMM_SMEM_FLOATS * 4>>>(
        skip_w, nullptr, skip_b,
        /*kchunks=*/16, /*as_r=*/64, /*as_c=*/16384,
        /*bs_b=*/(long)64 * TN, /*bs_c=*/(long)4 * 64 * TN,
        /*bsel=*/0, /*dsel=*/0, /*relu=*/1);

    // h2 = relu(out_w @ h1)
    k_gemm<<<dim3(TN / TT, 2, BN), 512, GEMM_SMEM_FLOATS * 4>>>(
        out_w, nullptr, nullptr,
        /*kchunks=*/4, /*as_r=*/256, /*as_c=*/64,
        /*bs_b=*/(long)256 * TN, /*bs_c=*/(long)64 * TN,
        /*bsel=*/1, /*dsel=*/1, /*relu=*/1);

    // out = shift_right(end_w @ h2)
    k_gemm<<<dim3(TN / TT, 2, BN), 512, GEMM_SMEM_FLOATS * 4>>>(
        end_w, out, nullptr,
        /*kchunks=*/4, /*as_r=*/256, /*as_c=*/64,
        /*bs_b=*/(long)256 * TN, /*bs_c=*/(long)64 * TN,
        /*bsel=*/2, /*dsel=*/2, /*relu=*/0);
}